// round 10
// baseline (speedup 1.0000x reference)
#include <cuda_runtime.h>
#include <cuda_bf16.h>

#define L 128
#define GRID 304   // two persistent 1024-thread CTAs per GB300 SM

__device__ __forceinline__ float sigmoidf(float x) {
    return 1.f / (1.f + __expf(-x));
}

// Persistent MFVI, tuned for bytes-in-flight (Little's law): 1024 threads,
// 4 rows/thread -> a CTA's whole 64KB tile is one LDG burst; 2 CTAs/SM +
// next-tile register prefetch keeps >=64KB outstanding per SM, vs the 16KB
// of the 512-thread version that capped DRAM at 48%.
//
// Warp w (0..31) owns rows 4w..4w+3; lane l owns k in [4l,4l+4) (coalesced
// LDG.128 row loads). Row sums: 2-stage multi-value shfl butterfly + 3
// cross-group shfls. mask2o exclusions (k==i, k==row) fold into the
// prefetch->live copy via compile-time-indexed selects.
__global__ __launch_bounds__(1024, 2)
void mfvi_kernel(const float* __restrict__ s_span,
                 const float* __restrict__ s_pair,
                 const unsigned int* __restrict__ mask,
                 float* __restrict__ out,
                 int BL)
{
    const int tid = threadIdx.x;
    const int w   = tid >> 5;              // warp id: rows 4w..4w+3
    const int l   = tid & 31;
    const int rg  = (w << 2) | (l & 3);    // row this lane owns after reduce
    const int k0  = 4 * l;                 // this lane's k range [k0, k0+4)

    __shared__ float sig[L];

    int tile = blockIdx.x;
    if (tile >= BL) return;

    // Prologue: stream first tile into the prefetch buffer.
    float4 nb[4];
    {
        const size_t base = (size_t)tile * L;
        #pragma unroll
        for (int r = 0; r < 4; ++r)
            nb[r] = __ldcs(reinterpret_cast<const float4*>(
                               s_pair + (base + ((w << 2) + r)) * L) + l);
    }

    for (; tile < BL; tile += GRID) {
        const int i = tile & (L - 1);
        const size_t base = (size_t)tile * L;

        // Consume prefetch buffer -> live regs, applying mask2o zeroing
        // (k == i or k == row).
        float a[16];
        #pragma unroll
        for (int r = 0; r < 4; ++r) {
            const int row = (w << 2) + r;
            a[4*r+0] = (k0+0 == i || k0+0 == row) ? 0.f : nb[r].x;
            a[4*r+1] = (k0+1 == i || k0+1 == row) ? 0.f : nb[r].y;
            a[4*r+2] = (k0+2 == i || k0+2 == row) ? 0.f : nb[r].z;
            a[4*r+3] = (k0+3 == i || k0+3 == row) ? 0.f : nb[r].w;
        }

        // Prefetch next tile: full 64KB burst, in flight under this tile's
        // compute (and the sibling CTA's compute).
        const int nt = tile + GRID;
        if (nt < BL) {
            const size_t nbase = (size_t)nt * L;
            #pragma unroll
            for (int r = 0; r < 4; ++r)
                nb[r] = __ldcs(reinterpret_cast<const float4*>(
                                   s_pair + (nbase + ((w << 2) + r)) * L) + l);
        }

        const float sj    = s_span[base + rg];
        const float maskf = (mask[base + rg] != 0u) ? 1.f : 0.f;

        float q = sj;
        #pragma unroll
        for (int it = 0; it < 3; ++it) {
            if (l < 4) sig[rg] = sigmoidf(q);
            __syncthreads();

            // One conflict-free LDS.128: lane l reads sig[4l..4l+3]
            float4 sg = *reinterpret_cast<const float4*>(sig + k0);

            float p[4];
            #pragma unroll
            for (int r = 0; r < 4; ++r)
                p[r] = a[4*r+0]*sg.x + a[4*r+1]*sg.y
                     + a[4*r+2]*sg.z + a[4*r+3]*sg.w;

            // 2-stage multi-value butterfly over lane bits 0..1:
            // after stage s, p[t] = row (t<<(s+1) | l&((2<<s)-1)) partial.
            #pragma unroll
            for (int s = 0; s < 2; ++s) {
                const int m  = 1 << s;
                const int my = (l >> s) & 1;
                #pragma unroll
                for (int t = 0; t < (2 >> s); ++t) {
                    float keep = my ? p[2*t+1] : p[2*t];
                    float give = my ? p[2*t]   : p[2*t+1];
                    float recv = __shfl_xor_sync(0xffffffffu, give, m);
                    p[t] = keep + recv;
                }
            }
            // Combine the eight 4-lane groups (distinct k-eighths of row)
            float tot = p[0];
            tot += __shfl_xor_sync(0xffffffffu, tot, 4);
            tot += __shfl_xor_sync(0xffffffffu, tot, 8);
            tot += __shfl_xor_sync(0xffffffffu, tot, 16);

            q = sj + maskf * tot;
            __syncthreads();   // sig reads done before next write
        }

        if (l < 4)
            out[base + rg] = sigmoidf(q);
        __syncthreads();       // sig stable before next tile's first write
    }
}

extern "C" void kernel_launch(void* const* d_in, const int* in_sizes, int n_in,
                              void* d_out, int out_size) {
    const float*        s_span = (const float*)d_in[0];
    const float*        s_pair = (const float*)d_in[1];
    const unsigned int* mask   = (const unsigned int*)d_in[2];
    float*              out    = (float*)d_out;

    const int BL = in_sizes[0] / L;   // B*L tiles
    mfvi_kernel<<<GRID, 1024>>>(s_span, s_pair, mask, out, BL);
}